// round 7
// baseline (speedup 1.0000x reference)
#include <cuda_runtime.h>
#include <cstdint>
#include <cstddef>

#define CB    8
#define CIN   64
#define COUT  64
#define TDIM  512
#define FDIM  161

constexpr int NFP   = 81;          // f-pairs
constexpr int NCHK  = 8;           // CIN chunks of 8
constexpr int TT    = 128;         // t-tile (GEMM N)
constexpr int NT    = TDIM / TT;   // 4
constexpr int NSTEP = 12;          // k8 steps per chunk (K_chunk = 96 = 8i * 12(m,n4))
constexpr int NTHR  = 512;         // 16 warps

// A tile per (fp,chunk): fragment-ordered [step][mtile][lane][4] tf32
constexpr int ATILE = NSTEP * 8 * 32 * 4;   // 12288 floats = 49152 B
constexpr int XTILE = 8 * 130 * 4;          // 4160 floats  = 16640 B  ([i][ts][n4])

constexpr int SM_A0 = 0;
constexpr int SM_A1 = 49152;
constexpr int SM_X0 = 98304;
constexpr int SM_X1 = SM_X0 + 16640;
constexpr int SM_TOTAL = SM_X1 + 16640;     // 131584 B

__device__ float g_wA[(size_t)NFP * NCHK * ATILE];   // 31.9 MB

// ---------------------------------------------------------------------------
__device__ __forceinline__ void cp_async16(uint32_t s, const void* g)
{
    asm volatile("cp.async.ca.shared.global [%0], [%1], 16;\n" :: "r"(s), "l"(g));
}
__device__ __forceinline__ void cp_async4z(uint32_t s, const void* g, bool ok)
{
    int sz = ok ? 4 : 0;
    asm volatile("cp.async.ca.shared.global [%0], [%1], 4, %2;\n" :: "r"(s), "l"(g), "r"(sz));
}
__device__ __forceinline__ uint32_t smem_u32(const void* p)
{
    uint32_t a;
    asm("{ .reg .u64 t; cvta.to.shared.u64 t, %1; cvt.u32.u64 %0, t; }" : "=r"(a) : "l"(p));
    return a;
}
__device__ __forceinline__ void mma_tf32(float& d0, float& d1, float& d2, float& d3,
                                         uint32_t a0, uint32_t a1, uint32_t a2, uint32_t a3,
                                         uint32_t b0, uint32_t b1)
{
    asm volatile("mma.sync.aligned.m16n8k8.row.col.f32.tf32.tf32.f32 "
                 "{%0,%1,%2,%3}, {%4,%5,%6,%7}, {%8,%9}, {%0,%1,%2,%3};"
                 : "+f"(d0), "+f"(d1), "+f"(d2), "+f"(d3)
                 : "r"(a0), "r"(a1), "r"(a2), "r"(a3), "r"(b0), "r"(b1));
}

// ---------------------------------------------------------------------------
// Weight transform: kernel[o][i][f][m][n] -> fragment-ordered A tiles.
// Per (fp,chunk): element at ((s*8+mt)*32+l)*4+r holds A[row][k] for
//   row = mt*16 + (l>>2) + 8*(r&1), k = s*8 + (l&3) + 4*(r>>1)
//   k -> i = ch*8 + k/12, m = (k%12)>>2, n4 = (k%12)&3; n = n4 - fh
// ---------------------------------------------------------------------------
__global__ void wtrans(const float* __restrict__ w)
{
    long idx = (long)blockIdx.x * 256 + threadIdx.x;
    const long total = (long)NFP * NCHK * ATILE;
    if (idx >= total) return;
    int e    = (int)(idx % ATILE);
    int tile = (int)(idx / ATILE);
    int ch = tile & 7;
    int fp = tile >> 3;
    int r  = e & 3;
    int l  = (e >> 2) & 31;
    int mt = (e >> 7) & 7;
    int s  = e >> 10;
    int row = mt * 16 + (l >> 2) + 8 * (r & 1);
    int k   = s * 8 + (l & 3) + 4 * (r >> 1);
    int i   = ch * 8 + k / 12;
    int rr  = k % 12;
    int m  = rr >> 2, n4 = rr & 3;
    int fh = row >> 6, o = row & 63;
    int f  = fp * 2 + fh;
    int n  = n4 - fh;
    float v = 0.f;
    if (n >= 0 && n < 3 && f < FDIM)
        v = w[(((size_t)(o * CIN + i) * FDIM + f) * 3 + m) * 3 + n];
    uint32_t tv; asm("cvt.rna.tf32.f32 %0, %1;" : "=r"(tv) : "f"(v));
    ((uint32_t*)g_wA)[idx] = tv;
}

// ---------------------------------------------------------------------------
// Main kernel: CTA = (fp, t-tile, b) -> out[b, 0:64, t0:t0+128, 2fp:2fp+2]
// 16 warps: warp_m = wid&3 (32 rows), warp_n = wid>>2 (32 cols)
// ---------------------------------------------------------------------------
__global__ void __launch_bounds__(NTHR, 1)
conv_mma(const float* __restrict__ x,
         const float* __restrict__ bias,
         float* __restrict__ out)
{
    extern __shared__ __align__(16) char smem[];
    const uint32_t sbase = smem_u32(smem);
    const int tid    = threadIdx.x;
    const int wid    = tid >> 5;
    const int lane   = tid & 31;
    const int warp_m = wid & 3;
    const int warp_n = wid >> 2;            // 0..3
    const int fp     = blockIdx.x;
    const int t0     = blockIdx.y * TT;
    const int b      = blockIdx.z;
    const int fbase  = fp * 2;
    const float* xb  = x + (size_t)b * CIN * TDIM * FDIM;

    // ---- per-thread B-fragment base offsets (chunk-invariant) ----
    // B elem addr (floats) = P + t*4, P = i*520 + m*4 + n4 for k = s*8+(lane&3)(+4)
    int P0[NSTEP], P1[NSTEP];
#pragma unroll
    for (int s = 0; s < NSTEP; s++) {
        int k0 = s * 8 + (lane & 3), k1 = k0 + 4;
        int i0 = k0 / 12, r0 = k0 % 12;
        int i1 = k1 / 12, r1 = k1 % 12;
        P0[s] = i0 * 520 + (r0 >> 2) * 4 + (r0 & 3);
        P1[s] = i1 * 520 + (r1 >> 2) * 4 + (r1 & 3);
    }

    // ---- accumulators init with bias ----
    float D[2][4][4];
#pragma unroll
    for (int w2 = 0; w2 < 2; w2++) {
#pragma unroll
        for (int h = 0; h < 2; h++) {
            int row = warp_m * 32 + w2 * 16 + (lane >> 2) + 8 * h;
            int fh = row >> 6, o = row & 63;
            int f = fbase + fh;
            float bv = (f < FDIM) ? bias[o * FDIM + f] : 0.f;
#pragma unroll
            for (int nt = 0; nt < 4; nt++) {
                D[w2][nt][2 * h + 0] = bv;
                D[w2][nt][2 * h + 1] = bv;
            }
        }
    }

    // ---- chunk prefetch: A (pre-packed, 16B copies) + x halo tile ----
    auto prefetch = [&](int c, int buf) {
        const float4* asrc = (const float4*)(g_wA + (size_t)(fp * NCHK + c) * ATILE);
        uint32_t ad = sbase + (buf ? SM_A1 : SM_A0);
#pragma unroll
        for (int j = 0; j < 6; j++) {
            int q = j * NTHR + tid;              // < 3072
            cp_async16(ad + q * 16, asrc + q);
        }
        const float* xc = xb + (size_t)c * 8 * TDIM * FDIM;
        uint32_t xd = sbase + (buf ? SM_X1 : SM_X0);
        for (int e = tid; e < XTILE; e += NTHR) {
            int n4  = e & 3;
            int rem = e >> 2;                    // i*130 + ts
            int i   = (int)(((unsigned)rem * 4033u) >> 19);   // rem/130
            int ts  = rem - i * 130;
            int gt  = t0 - 1 + ts;
            int gf  = fbase - 1 + n4;
            bool ok = (gt >= 0) & (gt < TDIM) & (gf >= 0) & (gf < FDIM);
            const float* src = xc + ((size_t)i * TDIM + (ok ? gt : 0)) * FDIM + (ok ? gf : 0);
            cp_async4z(xd + e * 4, src, ok);
        }
        asm volatile("cp.async.commit_group;\n");
    };

    prefetch(0, 0);

    for (int c = 0; c < NCHK; c++) {
        if (c + 1 < NCHK) {
            prefetch(c + 1, (c + 1) & 1);
            asm volatile("cp.async.wait_group 1;\n");
        } else {
            asm volatile("cp.async.wait_group 0;\n");
        }
        __syncthreads();

        const int buf = c & 1;
        const uint32_t* asb = (const uint32_t*)(smem + (buf ? SM_A1 : SM_A0));
        const uint32_t* xsb = (const uint32_t*)(smem + (buf ? SM_X1 : SM_X0));

#pragma unroll
        for (int s = 0; s < NSTEP; s++) {
            uint32_t a[2][4];
#pragma unroll
            for (int w2 = 0; w2 < 2; w2++) {
                const uint4* ap = (const uint4*)asb + ((s * 8 + warp_m * 2 + w2) * 32 + lane);
                uint4 av = *ap;
                a[w2][0] = av.x; a[w2][1] = av.y; a[w2][2] = av.z; a[w2][3] = av.w;
            }
            const int tB = warp_n * 32 + (lane >> 2);   // + nt*8
#pragma unroll
            for (int nt = 0; nt < 4; nt++) {
                int toff = (tB + nt * 8) * 4;
                uint32_t b0 = xsb[P0[s] + toff];
                uint32_t b1 = xsb[P1[s] + toff];
                mma_tf32(D[0][nt][0], D[0][nt][1], D[0][nt][2], D[0][nt][3],
                         a[0][0], a[0][1], a[0][2], a[0][3], b0, b1);
                mma_tf32(D[1][nt][0], D[1][nt][1], D[1][nt][2], D[1][nt][3],
                         a[1][0], a[1][1], a[1][2], a[1][3], b0, b1);
            }
        }
        __syncthreads();
    }

    // ---- epilogue: direct stores (row -> (fh,o), col -> t) ----
#pragma unroll
    for (int w2 = 0; w2 < 2; w2++) {
#pragma unroll
        for (int h = 0; h < 2; h++) {
            int row = warp_m * 32 + w2 * 16 + (lane >> 2) + 8 * h;
            int fh = row >> 6, o = row & 63;
            int f = fbase + fh;
            if (f < FDIM) {
                float* op = out + ((size_t)(b * COUT + o) * TDIM + t0 + warp_n * 32) * FDIM + f;
#pragma unroll
                for (int nt = 0; nt < 4; nt++) {
                    int tb = nt * 8 + (lane & 3) * 2;
                    op[(size_t)(tb    ) * FDIM] = D[w2][nt][2 * h + 0];
                    op[(size_t)(tb + 1) * FDIM] = D[w2][nt][2 * h + 1];
                }
            }
        }
    }
}

// ---------------------------------------------------------------------------
extern "C" void kernel_launch(void* const* d_in, const int* in_sizes, int n_in,
                              void* d_out, int out_size)
{
    const float* x    = (const float*)d_in[0];
    const float* w    = (const float*)d_in[1];
    const float* bias = (const float*)d_in[2];
    float* out        = (float*)d_out;

    cudaFuncSetAttribute(conv_mma, cudaFuncAttributeMaxDynamicSharedMemorySize, SM_TOTAL);

    const long total = (long)NFP * NCHK * ATILE;
    wtrans<<<(unsigned)((total + 255) / 256), 256>>>(w);

    dim3 grid(NFP, NT, CB);
    conv_mma<<<grid, NTHR, SM_TOTAL>>>(x, bias, out);
}